// round 17
// baseline (speedup 1.0000x reference)
#include <cuda_runtime.h>
#include <math_constants.h>
#include <cstdint>

// H=W=14, K=6, ST=2, xs={0,2,4,6,8}, M=5, B=32, C=1000
#define BB 32
#define CC 1000
#define HW 196
#define NVAL 145       // 144 rects + total
#define NPAIR 325      // unordered (u,v), u<=v, u,v in 0..24
#define NSTREAM 351    // 325 pair + 25 one-mask + 1 total
#define NCHUNK 8
#define CPB 125
#define T2 384
#define GRP 25
#define K1_WPB 8

__device__ float g_rect[BB * CC * NVAL];          // ~18.6 MB
__device__ float g_pval[BB * NCHUNK * NSTREAM];
__device__ int   g_pidx[BB * NCHUNK * NSTREAM];

// interval class id for [2a,2a+6) ∩ [2b,2b+6): d=0 -> 0..4 (w6),
// d=1 -> 5..8 (w4), d=2 -> 9..11 (w2), else empty
__device__ __forceinline__ int cls_id(int a, int b) {
    int d  = a > b ? a - b : b - a;
    int mn = a < b ? a : b;
    if (d == 0) return mn;
    if (d == 1) return 5 + mn;
    if (d == 2) return 9 + mn;
    return -1;
}

// interval id -> pair-unit bounds [lo2, hi2)
__device__ __forceinline__ void seg2(int ci, int& lo2, int& hi2) {
    if (ci < 5)      { lo2 = ci;     hi2 = ci + 3; }   // width 6
    else if (ci < 9) { lo2 = ci - 4; hi2 = ci - 2; }   // width 4
    else             { lo2 = ci - 7; hi2 = ci - 6; }   // width 2
}

// ---------------------------------------------------------------------------
// K1: warp-per-channel. Registers + shuffles; tiny 8x8 S2 table in smem.
// S2[rr][m] = sum over rows r<2rr of RP[r][m], RP = row col-pair prefix.
// rect[ri][ci] = S2[hi2r][hi2c]-S2[lo2r][hi2c]-S2[hi2r][lo2c]+S2[lo2r][lo2c]
// ---------------------------------------------------------------------------
__global__ __launch_bounds__(32 * K1_WPB) void k1_rects(const float* __restrict__ x) {
    const int lane = threadIdx.x & 31;
    const int w    = threadIdx.x >> 5;
    const int bc   = blockIdx.x * K1_WPB + w;

    __shared__ float s2all[K1_WPB][65];
    float* S2 = &s2all[w][0];            // S2[rr*8 + m]

    const int h = lane >> 4;             // 0: cols 0-7 ; 1: cols 8-13
    const int r = lane & 15;             // row 0..13 (r=14,15 idle)
    const bool act = (r < 14);

    const float* xp = x + (size_t)bc * HW + r * 14;

    // Phase A: per-row pair prefix in registers.
    // h0: rp1..rp4 = RP[r][1..4] ; h1: rp1..rp3 = RP[r][5..7] (after +c4)
    float rp1 = 0.f, rp2 = 0.f, rp3 = 0.f, rp4 = 0.f;
    if (act) {
        if (h == 0) {
            float2 a = *(const float2*)(xp + 0);
            float2 b = *(const float2*)(xp + 2);
            float2 c = *(const float2*)(xp + 4);
            float2 d = *(const float2*)(xp + 6);
            rp1 = a.x + a.y;
            rp2 = rp1 + (b.x + b.y);
            rp3 = rp2 + (c.x + c.y);
            rp4 = rp3 + (d.x + d.y);
        } else {
            float2 a = *(const float2*)(xp + 8);
            float2 b = *(const float2*)(xp + 10);
            float2 c = *(const float2*)(xp + 12);
            rp1 = a.x + a.y;
            rp2 = rp1 + (b.x + b.y);
            rp3 = rp2 + (c.x + c.y);
        }
    }
    // broadcast c4 (= RP[r][4], held in h0 lane r) to h1 lane 16+r
    float c4 = __shfl_sync(0xFFFFFFFFu, rp4, r);
    if (h == 1 && act) { rp1 += c4; rp2 += c4; rp3 += c4; }

    // Phase B: pair adjacent rows, then inclusive Kogge-Stone scan over k=r/2.
    float q1 = rp1 + __shfl_xor_sync(0xFFFFFFFFu, rp1, 1);
    float q2 = rp2 + __shfl_xor_sync(0xFFFFFFFFu, rp2, 1);
    float q3 = rp3 + __shfl_xor_sync(0xFFFFFFFFu, rp3, 1);
    float q4 = rp4 + __shfl_xor_sync(0xFFFFFFFFu, rp4, 1);
    const int k = r >> 1;                 // 0..6 valid
    #pragma unroll
    for (int s = 1; s < 8; s <<= 1) {
        float t1 = __shfl_up_sync(0xFFFFFFFFu, q1, 2 * s);
        float t2 = __shfl_up_sync(0xFFFFFFFFu, q2, 2 * s);
        float t3 = __shfl_up_sync(0xFFFFFFFFu, q3, 2 * s);
        float t4 = __shfl_up_sync(0xFFFFFFFFu, q4, 2 * s);
        if (k >= s) { q1 += t1; q2 += t2; q3 += t3; q4 += t4; }
    }

    float* go = g_rect + (size_t)bc * NVAL;

    // store S2 (even valid lanes hold inclusive T[k] = S2[k+1])
    if (act && (r & 1) == 0) {
        int row = (k + 1) * 8;
        if (h == 0) {
            S2[row + 1] = q1; S2[row + 2] = q2; S2[row + 3] = q3; S2[row + 4] = q4;
        } else {
            S2[row + 5] = q1; S2[row + 6] = q2; S2[row + 7] = q3;
        }
    }
    if (lane < 8)                S2[lane] = 0.f;            // rr = 0 row
    if (lane >= 8 && lane < 15)  S2[(lane - 7) * 8] = 0.f;  // m = 0 column
    if (lane == 28) go[144] = q3;                           // total = S2[7][7]
    __syncwarp();

    // Phase C: 144 rects, lanes 0..23 (ci = lane%12, row parity = lane/12)
    if (lane < 24) {
        int ci = lane, rbase = 0;
        if (lane >= 12) { ci = lane - 12; rbase = 1; }
        int lo2c, hi2c; seg2(ci, lo2c, hi2c);
        #pragma unroll
        for (int kk = 0; kk < 6; kk++) {
            int ri = rbase + 2 * kk;
            int lo2r, hi2r; seg2(ri, lo2r, hi2r);
            float v = S2[hi2r * 8 + hi2c] - S2[lo2r * 8 + hi2c]
                    - S2[hi2r * 8 + lo2c] + S2[lo2r * 8 + lo2c];
            go[ri * 12 + ci] = v;
        }
    }
}

// ---------------------------------------------------------------------------
// K2: per (chunk,b) partial argmax over 125 channels for 351 streams
// (symmetry: two[ij,pq] == two[pq,ij]).
// ---------------------------------------------------------------------------
__global__ __launch_bounds__(T2) void k2_argmax() {
    const int chunk = blockIdx.x;
    const int b     = blockIdx.y;
    const int t     = threadIdx.x;

    __shared__ float s[GRP][146];

    int offA = 145, offB = 145, offOv = 145;
    if (t < NPAIR) {
        int u = 0, t0 = t;
        while (t0 >= 25 - u) { t0 -= 25 - u; u++; }
        int v = u + t0;
        int i = u / 5, j = u % 5, p = v / 5, q = v % 5;
        offA = i * 12 + j;
        offB = p * 12 + q;
        int rip = cls_id(i, p), cjq = cls_id(j, q);
        offOv = (rip < 0 || cjq < 0) ? 145 : (rip * 12 + cjq);
    } else if (t < NPAIR + 25) {
        int ij = t - NPAIR;
        offA = (ij / 5) * 12 + (ij % 5);
    }                                   // t == 350: total stream

    if (t < GRP) s[t][145] = 0.f;       // persistent zero slot

    const int c0 = chunk * CPB;
    const float* gr = g_rect + ((size_t)b * CC + c0) * NVAL;

    float best = -CUDART_INF_F;
    int   bidx = 0;

    for (int r0 = 0; r0 < CPB; r0 += GRP) {
        __syncthreads();
        for (int idx = t; idx < GRP * NVAL; idx += T2) {
            int g = idx / NVAL, e = idx % NVAL;
            s[g][e] = gr[(size_t)(r0 + g) * NVAL + e];
        }
        __syncthreads();
        #pragma unroll
        for (int g = 0; g < GRP; g++) {
            float v = s[g][144] - s[g][offA] - s[g][offB] + s[g][offOv];
            if (v > best) { best = v; bidx = c0 + r0 + g; }   // strict >: first max
        }
    }

    if (t < NSTREAM) {
        int o = (b * NCHUNK + chunk) * NSTREAM + t;
        g_pval[o] = best;
        g_pidx[o] = bidx;
    }
}

// ---------------------------------------------------------------------------
// K3: reduce chunk partials; expand symmetric pairs; decide; float output.
// ---------------------------------------------------------------------------
__global__ __launch_bounds__(T2) void k3_decide(float* __restrict__ out) {
    const int b = blockIdx.x;
    const int t = threadIdx.x;

    __shared__ int spred[NSTREAM];
    __shared__ unsigned char cand[25];

    if (t < NSTREAM) {
        float bb = -CUDART_INF_F;
        int bi = 0;
        #pragma unroll
        for (int kc = 0; kc < NCHUNK; kc++) {
            int o = (b * NCHUNK + kc) * NSTREAM + t;
            float v = g_pval[o];
            int  id = g_pidx[o];
            if (v > bb) { bb = v; bi = id; }  // ties -> earlier chunk
        }
        spred[t] = bi;
    }
    __syncthreads();

    if (t < 25) {
        int om = spred[NPAIR + t];
        bool ag = true;
        #pragma unroll
        for (int pq = 0; pq < 25; pq++) {
            int a  = t < pq ? t : pq;
            int bb2 = t < pq ? pq : t;
            int idx = a * 25 - (a * (a - 1)) / 2 + (bb2 - a);
            ag = ag && (spred[idx] == om);
        }
        cand[t] = (ag && om != spred[350]) ? 1 : 0;
    }
    __syncthreads();

    if (t == 0) {
        int pred = spred[350];
        #pragma unroll
        for (int u = 0; u < 25; u++) {
            if (cand[u]) { pred = spred[NPAIR + u]; break; }   // first True
        }
        out[b] = (float)pred;   // __output__ is float32
    }
}

// ---------------------------------------------------------------------------
extern "C" void kernel_launch(void* const* d_in, const int* in_sizes, int n_in,
                              void* d_out, int out_size) {
    const float* x = (const float*)d_in[0];
    float* out = (float*)d_out;

    k1_rects<<<BB * CC / K1_WPB, 32 * K1_WPB>>>(x);
    dim3 g2(NCHUNK, BB);
    k2_argmax<<<g2, T2>>>();
    k3_decide<<<BB, T2>>>(out);
}